// round 12
// baseline (speedup 1.0000x reference)
#include <cuda_runtime.h>
#include <cstdint>

// KV-cache concat: out = [keys | values]
//   keys   = concat(key_cache[B,H,S,D],   key_states[B,H,1,D],   dim=-2)
//   values = concat(value_cache[B,H,S,D], value_states[B,H,1,D], dim=-2)
// B=8, H=32, S=4096, D=128, f32. Pure HBM-bound streaming copy.
//
// R12: copy-engine experiment — the one engine never measured. The output is
// exactly a pitched 2D layout: per tensor, 256 rows of 2MB (S*D*4) at a dst
// pitch of (S+1)*D*4. Two cudaMemcpy2DAsync D2D nodes (graph-capturable per
// harness rules) do the 2.146GB bulk on the CEs; a tiny kernel appends the
// 2MB of new state rows. SM-path best (R8): 305.6us wall @ 88% DRAM. CE wins
// iff its DRAM burst efficiency exceeds ~90.5% (covers the serialized state
// launch); otherwise revert to R8.

static constexpr int B = 8;
static constexpr int H = 32;
static constexpr int S = 4096;
static constexpr int D = 128;
static constexpr int D4 = D / 4;                         // 32 float4 per row
static constexpr int SLAB4 = (S + 1) * D4;               // 131104 float4 per (b,h)
static constexpr long long TENSOR4 = (long long)B * H * SLAB4;   // float4 per out tensor

static constexpr size_t ROW_BYTES  = (size_t)S * D * sizeof(float);        // 2 MB
static constexpr size_t DST_PITCH  = (size_t)(S + 1) * D * sizeof(float);  // 2.0005 MB
static constexpr int    N_ROWS     = B * H;              // 256

static constexpr int TPB = 256;
// 2 tensors * 256 bh * 32 float4 = 16384 float4 state writes.
__global__ __launch_bounds__(TPB)
void kv_state_kernel(const float4* __restrict__ key_states,
                     const float4* __restrict__ value_states,
                     float4* __restrict__ out)
{
    const int i = blockIdx.x * TPB + threadIdx.x;   // 0..16383
    const int t    = i >> 13;                       // 0/1
    const int bh   = (i >> 5) & 255;                // 0..255
    const int lane = i & 31;                        // 0..31

    const float4* __restrict__ states = t ? value_states : key_states;
    float4 v = __ldcs(states + ((long long)bh * D4 + lane));
    out[(long long)t * TENSOR4 + (long long)bh * SLAB4 + (long long)S * D4 + lane] = v;
}

extern "C" void kernel_launch(void* const* d_in, const int* in_sizes, int n_in,
                              void* d_out, int out_size)
{
    const float* key_cache    = (const float*)d_in[0];
    const float* value_cache  = (const float*)d_in[1];
    const float4* key_states   = (const float4*)d_in[2];
    const float4* value_states = (const float4*)d_in[3];
    float* out = (float*)d_out;

    // Bulk cache copies on the copy engines (pitched 2D, D2D, async —
    // graph-capturable).
    cudaMemcpy2DAsync(out, DST_PITCH,
                      key_cache, ROW_BYTES,
                      ROW_BYTES, N_ROWS,
                      cudaMemcpyDeviceToDevice);

    cudaMemcpy2DAsync(out + TENSOR4 * 4 /* floats */, DST_PITCH,
                      value_cache, ROW_BYTES,
                      ROW_BYTES, N_ROWS,
                      cudaMemcpyDeviceToDevice);

    // Append the single new row per (b,h) for both tensors (2 MB total).
    kv_state_kernel<<<16384 / TPB, TPB>>>(key_states, value_states,
                                          (float4*)d_out);
}

// round 13
// speedup vs baseline: 3.4718x; 3.4718x over previous
#include <cuda_runtime.h>
#include <cstdint>

// KV-cache concat: out = [keys | values]
//   keys   = concat(key_cache[B,H,S,D],   key_states[B,H,1,D],   dim=-2)
//   values = concat(value_cache[B,H,S,D], value_states[B,H,1,D], dim=-2)
// B=8, H=32, S=4096, D=128, f32. Pure HBM-bound streaming copy.
//
// FINAL (== R8, best measured: 305.6-306.4us wall over 4 runs, kernel
// 299.4-300.3us @ 88.0-88.2% DRAM, ~7.0 TB/s). Config space fully mapped
// over R1-R12, including the copy-engine alternative (R12: cudaMemcpy2DAsync
// pitched copies = 1065us, 3.5x SLOWER — CE decomposes the pitched copy into
// serialized per-row transfers; SM streaming wins decisively).
//  - single fused kernel (separate state launch: +5.8us serialized)
//  - branch-free bulk mapping: S*D4 = 2^17 -> out = j + (j>>17)*32
//  - UNROLL=8 front-batched float4 loads, u-stride = TPB strided window
//    (beats UNROLL=4/16 and per-warp-contiguous windows)
//  - TPB=512 (beats 256; ties 1024 with better kernel time)
//  - __ldcs/__stcs streaming hints (read-once/write-once)
//  - exact grid, no guards; state rows fused into first blocks per tensor
// DRAM pinned at the top of B300's 88-92% bidirectional-stream uniformity
// band; issue 2.7%, compute pipes idle; 2.15 GB traffic irreducible.

static constexpr int B = 8;
static constexpr int H = 32;
static constexpr int S = 4096;
static constexpr int D = 128;
static constexpr int D4 = D / 4;                        // 32 float4 per row
static constexpr int SLAB4 = (S + 1) * D4;              // 131104 float4 per (b,h)
static constexpr long long CACHE4 = (long long)B * H * S * D4;   // 2^25
static constexpr long long TENSOR4 = (long long)B * H * SLAB4;   // float4 per out tensor

static constexpr int TPB = 512;
static constexpr int UNROLL = 8;
static constexpr int BLOCKS_PER_TENSOR = (int)(CACHE4 / (TPB * UNROLL));  // 8192 exact
static constexpr int STATE_BLOCKS = (B * H * D4) / TPB; // 16

__global__ __launch_bounds__(TPB)
void kv_concat_fused_kernel(const float4* __restrict__ key_cache,
                            const float4* __restrict__ value_cache,
                            const float4* __restrict__ key_states,
                            const float4* __restrict__ value_states,
                            float4* __restrict__ out)
{
    const int t = blockIdx.y;                       // 0 = keys, 1 = values
    const float4* __restrict__ src = t ? value_cache : key_cache;
    float4* __restrict__ dst = out + (long long)t * TENSOR4;

    const long long j0 = (long long)blockIdx.x * (TPB * UNROLL) + threadIdx.x;

    // Front-batched loads (MLP = 8), streaming (evict-first) reads.
    float4 v[UNROLL];
#pragma unroll
    for (int u = 0; u < UNROLL; u++)
        v[u] = __ldcs(src + (j0 + (long long)u * TPB));

    // Streaming stores. out index = j + (bh<<5), bh = j>>17 (S*D4 = 2^17).
#pragma unroll
    for (int u = 0; u < UNROLL; u++) {
        long long j = j0 + (long long)u * TPB;
        __stcs(dst + (j + ((j >> 17) << 5)), v[u]);
    }

    // Fused state append: first STATE_BLOCKS blocks of each tensor write the
    // single new row per (b,h). One extra float4 per thread here (2 MB total).
    if (blockIdx.x < STATE_BLOCKS) {
        const int i = blockIdx.x * TPB + threadIdx.x;   // 0..8191
        const int bh   = i >> 5;                        // 0..255
        const int lane = i & 31;                        // 0..31
        const float4* __restrict__ states = t ? value_states : key_states;
        float4 sv = __ldcs(states + ((long long)bh * D4 + lane));
        dst[(long long)bh * SLAB4 + (long long)S * D4 + lane] = sv;
    }
}

extern "C" void kernel_launch(void* const* d_in, const int* in_sizes, int n_in,
                              void* d_out, int out_size)
{
    const float4* key_cache    = (const float4*)d_in[0];
    const float4* value_cache  = (const float4*)d_in[1];
    const float4* key_states   = (const float4*)d_in[2];
    const float4* value_states = (const float4*)d_in[3];
    float4* out = (float4*)d_out;

    dim3 grid(BLOCKS_PER_TENSOR, 2, 1);             // (8192, 2)
    kv_concat_fused_kernel<<<grid, TPB>>>(key_cache, value_cache,
                                          key_states, value_states, out);
}

// round 14
// speedup vs baseline: 3.4780x; 1.0018x over previous
#include <cuda_runtime.h>
#include <cstdint>

// KV-cache concat: out = [keys | values]
//   keys   = concat(key_cache[B,H,S,D],   key_states[B,H,1,D],   dim=-2)
//   values = concat(value_cache[B,H,S,D], value_states[B,H,1,D], dim=-2)
// B=8, H=32, S=4096, D=128, f32. Pure HBM-bound streaming copy.
//
// FINAL — best measured configuration, verified over 5 runs:
//   wall 305.63-306.78us, kernel 299.2-300.3us @ 88.0-88.3% DRAM,
//   7.17 TB/s effective on 2.146 GB of irreducible bidirectional traffic.
// Config space exhaustively mapped (R1-R13):
//  - single fused kernel (separate state launch: +5.8us serialized)
//  - branch-free bulk mapping: S*D4 = 2^17 -> out = j + (j>>17)*32
//  - UNROLL=8 front-batched float4 loads, u-stride = TPB strided window
//    (beats UNROLL=4/16 and per-warp-contiguous windows)
//  - TPB=512 (beats 256; ties 1024 with better kernel time)
//  - __ldcs/__stcs streaming hints (read-once/write-once)
//  - exact grid, no guards; state rows fused into first blocks per tensor
//  - copy engines rejected by measurement (R12: pitched memcpy2D = 1065us)
// DRAM sits at the top of B300's 88-92% bidirectional-stream uniformity
// band; issue 2.7%, compute pipes idle. This is the floor.

static constexpr int B = 8;
static constexpr int H = 32;
static constexpr int S = 4096;
static constexpr int D = 128;
static constexpr int D4 = D / 4;                        // 32 float4 per row
static constexpr int SLAB4 = (S + 1) * D4;              // 131104 float4 per (b,h)
static constexpr long long CACHE4 = (long long)B * H * S * D4;   // 2^25
static constexpr long long TENSOR4 = (long long)B * H * SLAB4;   // float4 per out tensor

static constexpr int TPB = 512;
static constexpr int UNROLL = 8;
static constexpr int BLOCKS_PER_TENSOR = (int)(CACHE4 / (TPB * UNROLL));  // 8192 exact
static constexpr int STATE_BLOCKS = (B * H * D4) / TPB; // 16

__global__ __launch_bounds__(TPB)
void kv_concat_fused_kernel(const float4* __restrict__ key_cache,
                            const float4* __restrict__ value_cache,
                            const float4* __restrict__ key_states,
                            const float4* __restrict__ value_states,
                            float4* __restrict__ out)
{
    const int t = blockIdx.y;                       // 0 = keys, 1 = values
    const float4* __restrict__ src = t ? value_cache : key_cache;
    float4* __restrict__ dst = out + (long long)t * TENSOR4;

    const long long j0 = (long long)blockIdx.x * (TPB * UNROLL) + threadIdx.x;

    // Front-batched loads (MLP = 8), streaming (evict-first) reads.
    float4 v[UNROLL];
#pragma unroll
    for (int u = 0; u < UNROLL; u++)
        v[u] = __ldcs(src + (j0 + (long long)u * TPB));

    // Streaming stores. out index = j + (bh<<5), bh = j>>17 (S*D4 = 2^17).
#pragma unroll
    for (int u = 0; u < UNROLL; u++) {
        long long j = j0 + (long long)u * TPB;
        __stcs(dst + (j + ((j >> 17) << 5)), v[u]);
    }

    // Fused state append: first STATE_BLOCKS blocks of each tensor write the
    // single new row per (b,h). One extra float4 per thread here (2 MB total).
    if (blockIdx.x < STATE_BLOCKS) {
        const int i = blockIdx.x * TPB + threadIdx.x;   // 0..8191
        const int bh   = i >> 5;                        // 0..255
        const int lane = i & 31;                        // 0..31
        const float4* __restrict__ states = t ? value_states : key_states;
        float4 sv = __ldcs(states + ((long long)bh * D4 + lane));
        dst[(long long)bh * SLAB4 + (long long)S * D4 + lane] = sv;
    }
}

extern "C" void kernel_launch(void* const* d_in, const int* in_sizes, int n_in,
                              void* d_out, int out_size)
{
    const float4* key_cache    = (const float4*)d_in[0];
    const float4* value_cache  = (const float4*)d_in[1];
    const float4* key_states   = (const float4*)d_in[2];
    const float4* value_states = (const float4*)d_in[3];
    float4* out = (float4*)d_out;

    dim3 grid(BLOCKS_PER_TENSOR, 2, 1);             // (8192, 2)
    kv_concat_fused_kernel<<<grid, TPB>>>(key_cache, value_cache,
                                          key_states, value_states, out);
}